// round 10
// baseline (speedup 1.0000x reference)
#include <cuda_runtime.h>

#define HH   1024
#define WW   1024
#define CIN  8
#define COUT 8
#define KS   31
#define PAD  15
#define TILE 32
#define SMW  64          // smem row stride (floats)
#define INT_ 62          // input tile edge = TILE + KS - 1

// Transposed weights: [cin][ky*31+kx][cout]  (8*961*8 floats = 246 KB)
__device__ float g_wT[CIN * KS * KS * COUT];

__global__ void transpose_w_kernel(const float* __restrict__ w) {
    int i = blockIdx.x * blockDim.x + threadIdx.x;
    const int total = COUT * CIN * KS * KS;
    if (i >= total) return;
    int kx = i % KS;
    int t  = i / KS;
    int ky = t % KS;  t /= KS;
    int ci = t % CIN;
    int co = t / CIN;
    g_wT[(ci * KS * KS + ky * KS + kx) * COUT + co] = w[i];
}

// One block = one 32x32 output tile for ONE ci and ALL 8 co's.
// out[co, ci, y, x] = sum_{ky,kx} signal[ci, y+ky-15, x+kx-15] * w[co,ci,ky,kx] + bias[ci]
__global__ __launch_bounds__(256, 2)
void conv31_kernel(const float* __restrict__ sig,
                   const float* __restrict__ bias,
                   float* __restrict__ out)
{
    __shared__ float s_in[INT_ * SMW];          // 62 x 64 floats = 15872 B
    __shared__ float s_w[KS * KS * COUT];       // 961 x 8 floats = 30752 B

    const int tx  = threadIdx.x;                // 0..31 (lane)
    const int ty  = threadIdx.y;                // 0..7
    const int tid = ty * 32 + tx;
    const int bx  = blockIdx.x * TILE;
    const int by  = blockIdx.y * TILE;
    const int ci  = blockIdx.z;                 // 0..7

    // --- load 62x62 input tile for this ci (zero-padded at image borders) ---
    {
        const float* sp = sig + ci * HH * WW;
        for (int idx = tid; idx < INT_ * INT_; idx += 256) {
            int r  = idx / INT_;
            int c  = idx - r * INT_;
            int gy = by + r - PAD;
            int gx = bx + c - PAD;
            float v = 0.f;
            if ((unsigned)gy < (unsigned)HH && (unsigned)gx < (unsigned)WW)
                v = sp[gy * WW + gx];
            s_in[r * SMW + c] = v;
        }
    }

    // --- load transposed weights for this ci (float4 copies) ---
    {
        const float4* wsrc = (const float4*)(g_wT + ci * KS * KS * COUT);
        float4* wdst = (float4*)s_w;
        for (int idx = tid; idx < (KS * KS * COUT) / 4; idx += 256)
            wdst[idx] = wsrc[idx];
    }
    __syncthreads();

    float acc[4][COUT];
#pragma unroll
    for (int r = 0; r < 4; r++)
#pragma unroll
        for (int c = 0; c < COUT; c++) acc[r][c] = 0.f;

    // --- main compute: FMA-pipe-bound ---
    for (int ky = 0; ky < KS; ky++) {
        const float*  srow = s_in + (ty + ky) * SMW + tx;
        const float4* wrow = (const float4*)(s_w + ky * KS * COUT);
#pragma unroll
        for (int kx = 0; kx < KS; kx++) {
            const float4 w0 = wrow[kx * 2 + 0];   // couts 0..3 (broadcast LDS.128)
            const float4 w1 = wrow[kx * 2 + 1];   // couts 4..7
#pragma unroll
            for (int ry = 0; ry < 4; ry++) {
                const float s = srow[ry * 8 * SMW + kx];   // conflict-free: lane==tx
                acc[ry][0] += s * w0.x;
                acc[ry][1] += s * w0.y;
                acc[ry][2] += s * w0.z;
                acc[ry][3] += s * w0.w;
                acc[ry][4] += s * w1.x;
                acc[ry][5] += s * w1.y;
                acc[ry][6] += s * w1.z;
                acc[ry][7] += s * w1.w;
            }
        }
    }

    // --- epilogue: +bias[ci], write 8 co planes, coalesced ---
    const float b = bias[ci];
#pragma unroll
    for (int co = 0; co < COUT; co++) {
        float* op = out + (co * CIN + ci) * HH * WW;
#pragma unroll
        for (int ry = 0; ry < 4; ry++) {
            const int y = by + ry * 8 + ty;
            const int x = bx + tx;
            op[y * WW + x] = acc[ry][co] + b;
        }
    }
}

extern "C" void kernel_launch(void* const* d_in, const int* in_sizes, int n_in,
                              void* d_out, int out_size)
{
    const float* sig  = (const float*)d_in[0];   // [1,8,1024,1024]
    const float* w    = (const float*)d_in[1];   // [8,8,31,31]
    const float* bias = (const float*)d_in[2];   // [8]
    float* out = (float*)d_out;                  // [8,8,1024,1024] (co, ci, y, x)

    const int wtotal = COUT * CIN * KS * KS;
    transpose_w_kernel<<<(wtotal + 255) / 256, 256>>>(w);

    dim3 grid(WW / TILE, HH / TILE, CIN);  // 32 x 32 x 8 = 8192 blocks
    dim3 block(32, 8);                     // 256 threads
    conv31_kernel<<<grid, block>>>(sig, bias, out);
}

// round 15
// speedup vs baseline: 1.0162x; 1.0162x over previous
#include <cuda_runtime.h>

#define HH   1024
#define WW   1024
#define CIN  8
#define COUT 8
#define KS   31
#define PAD  15
#define TILE 32
#define SMW  64          // smem row stride (floats)
#define INT_ 62          // input tile edge = TILE + KS - 1

// Transposed weights: [cin][ky*31+kx][cout]  (8*961*8 floats = 246 KB)
__device__ float g_wT[CIN * KS * KS * COUT];

__global__ void transpose_w_kernel(const float* __restrict__ w) {
    int i = blockIdx.x * blockDim.x + threadIdx.x;
    const int total = COUT * CIN * KS * KS;
    if (i >= total) return;
    int kx = i % KS;
    int t  = i / KS;
    int ky = t % KS;  t /= KS;
    int ci = t % CIN;
    int co = t / CIN;
    g_wT[(ci * KS * KS + ky * KS + kx) * COUT + co] = w[i];
}

// Packed fp32x2 helpers (sm_103a): one issue slot, two fp32 FMAs.
__device__ __forceinline__ unsigned long long splat2(float s) {
    unsigned long long r;
    asm("mov.b64 %0, {%1, %1};" : "=l"(r) : "f"(s));
    return r;
}
__device__ __forceinline__ void fma2(unsigned long long& d,
                                     unsigned long long a,
                                     unsigned long long b) {
    asm("fma.rn.f32x2 %0, %1, %2, %0;" : "+l"(d) : "l"(a), "l"(b));
}

// One block = one 32x32 output tile for ONE ci and ALL 8 co's.
// out[co, ci, y, x] = sum_{ky,kx} signal[ci, y+ky-15, x+kx-15] * w[co,ci,ky,kx] + bias[ci]
__global__ __launch_bounds__(256, 2)
void conv31_kernel(const float* __restrict__ sig,
                   const float* __restrict__ bias,
                   float* __restrict__ out)
{
    __shared__ float s_in[INT_ * SMW];          // 15872 B
    __shared__ float s_w[KS * KS * COUT];       // 30752 B

    const int tx  = threadIdx.x;                // 0..31 (lane)
    const int ty  = threadIdx.y;                // 0..7
    const int tid = ty * 32 + tx;
    const int bx  = blockIdx.x * TILE;
    const int by  = blockIdx.y * TILE;
    const int ci  = blockIdx.z;                 // 0..7

    // --- load 62x62 input tile for this ci (zero-padded at image borders) ---
    {
        const float* sp = sig + ci * HH * WW;
        for (int idx = tid; idx < INT_ * INT_; idx += 256) {
            int r  = idx / INT_;
            int c  = idx - r * INT_;
            int gy = by + r - PAD;
            int gx = bx + c - PAD;
            float v = 0.f;
            if ((unsigned)gy < (unsigned)HH && (unsigned)gx < (unsigned)WW)
                v = sp[gy * WW + gx];
            s_in[r * SMW + c] = v;
        }
    }

    // --- load transposed weights for this ci (float4 copies) ---
    {
        const float4* wsrc = (const float4*)(g_wT + ci * KS * KS * COUT);
        float4* wdst = (float4*)s_w;
        for (int idx = tid; idx < (KS * KS * COUT) / 4; idx += 256)
            wdst[idx] = wsrc[idx];
    }
    __syncthreads();

    // acc2[ry][p] = f32x2 accumulator for couts {2p, 2p+1}
    unsigned long long acc2[4][4];
#pragma unroll
    for (int r = 0; r < 4; r++)
#pragma unroll
        for (int p = 0; p < 4; p++) acc2[r][p] = 0ull;

    // --- main compute: packed f32x2 FMA, issue-bound ---
    for (int ky = 0; ky < KS; ky++) {
        const float* srow = s_in + (ty + ky) * SMW + tx;
        // consecutive couts are adjacent -> LDS.64 yields pre-packed f32x2 weights
        const unsigned long long* wrow =
            (const unsigned long long*)(s_w + ky * KS * COUT);
#pragma unroll
        for (int kx = 0; kx < KS; kx++) {
            const unsigned long long w01 = wrow[kx * 4 + 0];
            const unsigned long long w23 = wrow[kx * 4 + 1];
            const unsigned long long w45 = wrow[kx * 4 + 2];
            const unsigned long long w67 = wrow[kx * 4 + 3];
#pragma unroll
            for (int ry = 0; ry < 4; ry++) {
                const float s = srow[ry * 8 * SMW + kx];   // conflict-free
                const unsigned long long s2 = splat2(s);
                fma2(acc2[ry][0], s2, w01);
                fma2(acc2[ry][1], s2, w23);
                fma2(acc2[ry][2], s2, w45);
                fma2(acc2[ry][3], s2, w67);
            }
        }
    }

    // --- epilogue: +bias[ci], write 8 co planes, coalesced ---
    const float b = bias[ci];
#pragma unroll
    for (int p = 0; p < 4; p++) {
#pragma unroll
        for (int half = 0; half < 2; half++) {
            const int co = 2 * p + half;
            float* op = out + (co * CIN + ci) * HH * WW;
#pragma unroll
            for (int ry = 0; ry < 4; ry++) {
                float lo, hi;
                asm("mov.b64 {%0, %1}, %2;"
                    : "=f"(lo), "=f"(hi) : "l"(acc2[ry][p]));
                const float v = half ? hi : lo;
                const int y = by + ry * 8 + ty;
                const int x = bx + tx;
                op[y * WW + x] = v + b;
            }
        }
    }
}

extern "C" void kernel_launch(void* const* d_in, const int* in_sizes, int n_in,
                              void* d_out, int out_size)
{
    const float* sig  = (const float*)d_in[0];   // [1,8,1024,1024]
    const float* w    = (const float*)d_in[1];   // [8,8,31,31]
    const float* bias = (const float*)d_in[2];   // [8]
    float* out = (float*)d_out;                  // [8,8,1024,1024] (co, ci, y, x)

    const int wtotal = COUT * CIN * KS * KS;
    transpose_w_kernel<<<(wtotal + 255) / 256, 256>>>(w);

    dim3 grid(WW / TILE, HH / TILE, CIN);  // 32 x 32 x 8 = 8192 blocks
    dim3 block(32, 8);                     // 256 threads
    conv31_kernel<<<grid, block>>>(sig, bias, out);
}